// round 5
// baseline (speedup 1.0000x reference)
#include <cuda_runtime.h>

#define BATCH   16
#define CHN     512
#define HW      4096            // 64*64
#define NCLS    5
#define NSEG    (BATCH * NCLS)  // 80
#define NPIX    (BATCH * HW)    // 65536
#define CCHUNKS 32
#define CPER    (CHN / CCHUNKS) // 16
#define JBLKS   4
#define BPB     (CCHUNKS * JBLKS)     // 128 blocks per batch
#define NBLOCKS (BATCH * BPB)         // 2048
#define BETA    2.0f
#define EPS2    (0.001f * 0.001f)

// per-block partial segment sums (sum of squared diffs, not yet /CHN)
__device__ float g_bsum[NBLOCKS * NCLS];
// per-(b,jblk) mask histogram counts (only k==0 blocks write)
__device__ float g_bcnt[BATCH * JBLKS * NCLS];
// last-block-done counter; reset to 0 by the finalizing block each run
__device__ unsigned int g_done;

__global__ void __launch_bounds__(256)
frl_fused(const float4* __restrict__ rec,
          const float4* __restrict__ ali,
          const int4*  __restrict__ mask,
          float* __restrict__ out) {
    __shared__ float ssum[NCLS];
    __shared__ float scnt[NCLS];
    const int bid  = blockIdx.x;
    const int tid  = threadIdx.x;
    const int jblk = bid & 3;                 // 4 j-blocks of 256 float4s
    const int k    = (bid >> 2) & (CCHUNKS - 1);
    const int b    = bid >> 7;                // 128 blocks per batch

    if (tid < NCLS) { ssum[tid] = 0.0f; scnt[tid] = 0.0f; }
    __syncthreads();

    const int j = jblk * 256 + tid;           // float4 index within image
    const int S = HW / 4;                     // 1024 float4 per channel plane
    int base = (b * CHN + k * CPER) * S + j;

    float ax = 0.f, ay = 0.f, az = 0.f, aw = 0.f;
    #pragma unroll
    for (int c = 0; c < CPER; ++c) {
        float4 r = __ldcs(&rec[base + c * S]);
        float4 a = __ldcs(&ali[base + c * S]);
        float dx = r.x - a.x, dy = r.y - a.y, dz = r.z - a.z, dw = r.w - a.w;
        ax += dx * dx; ay += dy * dy; az += dz * dz; aw += dw * dw;
    }

    const int4 m = mask[b * S + j];
    atomicAdd(&ssum[m.x], ax);
    atomicAdd(&ssum[m.y], ay);
    atomicAdd(&ssum[m.z], az);
    atomicAdd(&ssum[m.w], aw);
    if (k == 0) {
        atomicAdd(&scnt[m.x], 1.0f);
        atomicAdd(&scnt[m.y], 1.0f);
        atomicAdd(&scnt[m.z], 1.0f);
        atomicAdd(&scnt[m.w], 1.0f);
    }
    __syncthreads();

    if (tid < NCLS) {
        g_bsum[bid * NCLS + tid] = ssum[tid];
        if (k == 0)
            g_bcnt[(b * JBLKS + jblk) * NCLS + tid] = scnt[tid];
    }

    // ---- last-block-done election ----
    __threadfence();
    __syncthreads();
    __shared__ bool amLast;
    if (tid == 0) {
        unsigned int prev = atomicAdd(&g_done, 1u);
        amLast = (prev == NBLOCKS - 1);
    }
    __syncthreads();
    if (!amLast) return;

    // ================= finalize (one block, 256 threads) =================
    __shared__ float s_part[2 * NSEG];   // 160 half-sums
    __shared__ float s_sum[NSEG];        // segment sum of lm
    __shared__ float s_avg[NSEG];        // segment mean of lm
    __shared__ float red[256];

    // Phase A: 160 threads each sum 64 of the 128 partials of one segment.
    if (tid < 2 * NSEG) {
        const int seg = tid >> 1, half = tid & 1;
        const int sb = seg / NCLS, cls = seg % NCLS;
        int p = (sb * BPB + half * 64) * NCLS + cls;
        float s = 0.0f;
        #pragma unroll 8
        for (int i = 0; i < 64; ++i)
            s += __ldcg(&g_bsum[p + i * NCLS]);
        s_part[tid] = s;
    }
    __syncthreads();

    if (tid < NSEG) {
        const int sb = tid / NCLS, cls = tid % NCLS;
        float cnt = 0.0f;
        #pragma unroll
        for (int jb = 0; jb < JBLKS; ++jb)
            cnt += __ldcg(&g_bcnt[(sb * JBLKS + jb) * NCLS + cls]);
        const float lmsum = (s_part[2 * tid] + s_part[2 * tid + 1]) * (1.0f / CHN);
        s_sum[tid] = lmsum;
        s_avg[tid] = lmsum / fmaxf(cnt, 1.0f);  // empty segs -> 0, can't win max
    }

    // max over segment means
    red[tid] = (tid < NSEG) ? s_avg[tid] : 0.0f;
    __syncthreads();
    #pragma unroll
    for (int s2 = 128; s2 > 0; s2 >>= 1) {
        if (tid < s2) red[tid] = fmaxf(red[tid], red[tid + s2]);
        __syncthreads();
    }
    const float wmax = red[0];
    __syncthreads();

    // weighted sum: loss = (1/NPIX) * sum_seg segsum * (clip(w)*BETA + 1)
    float part = 0.0f;
    if (tid < NSEG) {
        float a = s_avg[tid];
        float w = (wmax > 0.0f) ? a / (wmax + EPS2) : a + EPS2;
        w = fminf(fmaxf(w, 0.0f), 1.0f);
        part = s_sum[tid] * (w * BETA + 1.0f);
    }
    red[tid] = part;
    __syncthreads();
    #pragma unroll
    for (int s2 = 128; s2 > 0; s2 >>= 1) {
        if (tid < s2) red[tid] += red[tid + s2];
        __syncthreads();
    }
    if (tid == 0) {
        g_done = 0;                       // reset for next (graph) replay
        out[0] = red[0] * (1.0f / NPIX);
    }
}

// ---------------------------------------------------------------- launch
extern "C" void kernel_launch(void* const* d_in, const int* in_sizes, int n_in,
                              void* d_out, int out_size) {
    const float4* rec  = (const float4*)d_in[0];
    const float4* ali  = (const float4*)d_in[1];
    const int4*   mask = (const int4*)d_in[2];
    float*        out  = (float*)d_out;

    frl_fused<<<NBLOCKS, 256>>>(rec, ali, mask, out);
}